// round 10
// baseline (speedup 1.0000x reference)
#include <cuda_runtime.h>
#include <cstdint>

#define B_    16
#define T_    1024
#define V_    8192
#define H_    1024
#define NBLK  128
#define BTV   134217728   // B_*T_*V_

// ---------------------------------------------------------------------------
// Device-global scratch (allocation is forbidden) + barrier state.
//   g_hs  : [t][k][b] fp32 (GEMM A tiles; tile rows m = t*16+b)
//   g_hT  : ping-pong h exchange in PAIR layout: idx = (j>>1)*32 + b*2 + (j&1)
//   g_WyT : Wy transposed to [h][v] (GEMM B tiles, cp.async-friendly)
// ---------------------------------------------------------------------------
__device__ float    g_hs[(size_t)T_ * B_ * H_];    // 64 MB
__device__ float    g_WyT[(size_t)H_ * V_];        // 32 MB
__device__ float    g_hT[2][B_ * H_];
__device__ unsigned g_bar_leaf[8 * 64];            // leaf counters, 256B stride
__device__ unsigned g_bar_root  = 0;
__device__ unsigned g_bar_sense = 0;

extern __shared__ float smem_dyn[];

// ---------------------------------------------------------------------------
// Packed f32x2 helpers (FFMA2 path: only reachable via PTX fma.rn.f32x2)
// ---------------------------------------------------------------------------
__device__ __forceinline__ unsigned long long pack2(float x, float y) {
    unsigned long long r;
    asm("mov.b64 %0, {%1, %2};" : "=l"(r) : "f"(x), "f"(y));
    return r;
}
__device__ __forceinline__ void fma2(unsigned long long &d,
                                     unsigned long long a,
                                     unsigned long long b) {
    asm("fma.rn.f32x2 %0, %1, %2, %0;" : "+l"(d) : "l"(a), "l"(b));
}
__device__ __forceinline__ void unpack2(unsigned long long v, float &lo, float &hi) {
    asm("mov.b64 {%0, %1}, %2;" : "=f"(lo), "=f"(hi) : "l"(v));
}
__device__ __forceinline__ uint32_t smem_u32(const void* p) {
    uint32_t a;
    asm("{ .reg .u64 t; cvta.to.shared.u64 t, %1; cvt.u32.u64 %0, t; }"
        : "=r"(a) : "l"(p));
    return a;
}
__device__ __forceinline__ void cp16(uint32_t dst, const void* src) {
    asm volatile("cp.async.cg.shared.global [%0], [%1], 16;"
                 :: "r"(dst), "l"(src) : "memory");
}

// ---------------------------------------------------------------------------
// Kernel 0: transpose Wy [V,H] -> g_WyT [H,V].  Coalesced both sides.
// ---------------------------------------------------------------------------
__global__ void __launch_bounds__(256)
transpose_wy_kernel(const float* __restrict__ Wy)
{
    __shared__ float tile[32][33];
    const int v0 = (int)blockIdx.x * 32;
    const int h0 = (int)blockIdx.y * 32;
    const int tx = threadIdx.x & 31;
    const int ty = threadIdx.x >> 5;          // 0..7
    #pragma unroll
    for (int s = 0; s < 32; s += 8)
        tile[ty + s][tx] = __ldg(&Wy[(size_t)(v0 + ty + s) * H_ + h0 + tx]);
    __syncthreads();
    #pragma unroll
    for (int s = 0; s < 32; s += 8)
        g_WyT[(size_t)(h0 + ty + s) * V_ + v0 + tx] = tile[tx][ty + s];
}

// ---------------------------------------------------------------------------
// Kernel 1: persistent RNN recurrence (verified R9 body; barrier replaced by
// a two-level tree: 8 leaf counters x 16 arrivals -> root -> sense flip).
//   h_t[b][j] = tanh( Wx_w[j, x[b,t]] + Wx_b[j] + sum_k h_{t-1}[b][k]*Wh[j][k] )
// 128 blocks x 128 threads; block owns 8 j, all 16 b.
// ---------------------------------------------------------------------------
__global__ void __launch_bounds__(128, 1)
rnn_recurrence_kernel(const int*   __restrict__ x,
                      const float* __restrict__ h0,
                      const float* __restrict__ Wx,
                      const float* __restrict__ Wxb,
                      const float* __restrict__ Wh,
                      float*       __restrict__ out,
                      int out_size)
{
    float* h_s  = smem_dyn;            // 16384 floats: h_{t-1} pair layout
    float* wh_s = smem_dyn + 16384;    //  8192 floats: Wh rows [jl][k]

    const int tid = threadIdx.x;
    const int j0  = (int)blockIdx.x * 8;
    const int jl  = tid >> 4;          // 0..7
    const int j   = j0 + jl;
    const int b   = tid & 15;

    {   // one-time: stage this block's 8 Wh rows (32 KB)
        const float4* src = (const float4*)(Wh + (size_t)j0 * H_);
        float4*       dst = (float4*)wh_s;
        #pragma unroll
        for (int s = 0; s < 16; s++)
            dst[tid + s * 128] = src[tid + s * 128];
    }

    const float  wxb   = Wxb[j];
    const float* wxrow = Wx + (size_t)j * V_;
    const int*   xrow  = x + b * T_;
    const float* whs   = wh_s + jl * H_;
    const int    pidx  = ((j >> 1) << 5) + (b << 1) + (j & 1);
    float*       hout  = g_hs + (size_t)j * 16 + b;    // [t][k][b], k = j

    for (int t = 0; t < T_; t++) {
        // ---- stage h_{t-1} into shared (pair layout) ----
        if (t == 0) {
            for (int i = tid; i < B_ * H_; i += 128) {
                int bb = (i >> 1) & 15;
                int kk = ((i >> 5) << 1) | (i & 1);
                h_s[i] = h0[bb * H_ + kk];
            }
        } else {
            const float4* src = (const float4*)(g_hT[(t - 1) & 1]);
            float4*       dst = (float4*)h_s;
            #pragma unroll
            for (int s = 0; s < 32; s++)
                dst[tid + s * 128] = __ldcg(src + tid + s * 128);
        }
        __syncthreads();

        // ---- embedding gather (L2-resident Wx) ----
        int   xi = __ldg(xrow + t);
        float e  = __ldg(wxrow + xi) + wxb;

        // ---- dot(h_{t-1}[b][:], Wh[j][:]) via f32x2, 8 chains ----
        unsigned long long acc2[8];
        #pragma unroll
        for (int i = 0; i < 8; i++) acc2[i] = 0ull;

        const char* hbase = (const char*)h_s + b * 8;
        #pragma unroll 2
        for (int kp = 0; kp < 512; kp += 8) {           // 16 k per iter
            ulonglong2 w01 = *(const ulonglong2*)(whs + 2 * kp);
            ulonglong2 w23 = *(const ulonglong2*)(whs + 2 * kp + 4);
            ulonglong2 w45 = *(const ulonglong2*)(whs + 2 * kp + 8);
            ulonglong2 w67 = *(const ulonglong2*)(whs + 2 * kp + 12);
            const char* hp = hbase + (size_t)kp * 128;
            fma2(acc2[0], *(const unsigned long long*)(hp + 0 * 128), w01.x);
            fma2(acc2[1], *(const unsigned long long*)(hp + 1 * 128), w01.y);
            fma2(acc2[2], *(const unsigned long long*)(hp + 2 * 128), w23.x);
            fma2(acc2[3], *(const unsigned long long*)(hp + 3 * 128), w23.y);
            fma2(acc2[4], *(const unsigned long long*)(hp + 4 * 128), w45.x);
            fma2(acc2[5], *(const unsigned long long*)(hp + 5 * 128), w45.y);
            fma2(acc2[6], *(const unsigned long long*)(hp + 6 * 128), w67.x);
            fma2(acc2[7], *(const unsigned long long*)(hp + 7 * 128), w67.y);
        }
        float dot;
        {
            float s0 = 0.f, s1 = 0.f;
            #pragma unroll
            for (int i = 0; i < 8; i += 2) {
                float l, h;
                unpack2(acc2[i], l, h);     s0 += l + h;
                unpack2(acc2[i + 1], l, h); s1 += l + h;
            }
            dot = s0 + s1;
        }
        float hv = tanhf(e + dot);

        // exchange buffer (pair layout; fully coalesced) + GEMM A matrix
        __stcg(&g_hT[t & 1][pidx], hv);
        __stcg(hout + (size_t)t * (B_ * H_), hv);

        if (t == T_ - 1 && out_size >= BTV + B_ * H_)
            out[(size_t)BTV + b * H_ + j] = hv;          // h_final [B][H]

        // ---- two-level grid barrier (sense-reversing, replay-safe) ----
        __threadfence();
        __syncthreads();
        if (tid == 0) {
            unsigned gen  = *((volatile unsigned*)&g_bar_sense);
            unsigned* lc  = &g_bar_leaf[((unsigned)blockIdx.x & 7u) * 64u];
            unsigned  pos = atomicAdd(lc, 1u);
            if (pos == 15u) {                 // last of this leaf's 16 blocks
                atomicExch(lc, 0u);
                unsigned r = atomicAdd(&g_bar_root, 1u);
                if (r == 7u) {                // last leaf overall
                    atomicExch(&g_bar_root, 0u);
                    __threadfence();
                    atomicAdd(&g_bar_sense, 1u);
                }
            }
            while (*((volatile unsigned*)&g_bar_sense) == gen) { }
        }
        __syncthreads();
        __threadfence();
    }
}

// ---------------------------------------------------------------------------
// Kernel 2: output GEMM (FFMA2), 2-stage cp.async pipeline, zero transposes.
//   logits[b][t][v] = sum_k hs[t][k][b] * WyT[k][v] + Wyb[v]
// A[m][k] = g_hs[t][k][b], m = t*16+b; B[k][n] = g_WyT[k][n].
// 128x128x16 tiles, 256 threads; compute core = verified R9 conflict-free
// interleaved-quad micro-tiles (8x8 per thread via f32x2).
// ---------------------------------------------------------------------------
#define BK   16
#define LDAS 132   // 128 + pad 4 (row = 528 B, 16B-aligned)

__global__ void __launch_bounds__(256)
gemm_logits_kernel(const float* __restrict__ Wyb,
                   float*       __restrict__ out)
{
    __shared__ float As[2][BK][LDAS];
    __shared__ float Bs[2][BK][LDAS];

    const int tid = threadIdx.x;
    const int tn  = tid & 15;
    const int tm  = tid >> 4;
    const int n0  = (int)blockIdx.x * 128;
    const int t0  = (int)blockIdx.y * 8;     // m0 = t0*16

    // A chunk map (c in [0,512)): bh=c&3, k=(c>>2)&15, t=c>>6  (gmem-contiguous)
    // B chunk map (c in [0,512)): n4=c&31, k=c>>5               (gmem-contiguous)
    const int ac0 = tid, ac1 = tid + 256;
    const int a0_bh = ac0 & 3, a0_k = (ac0 >> 2) & 15, a0_t = ac0 >> 6;
    const int a1_bh = ac1 & 3, a1_k = (ac1 >> 2) & 15, a1_t = ac1 >> 6;
    const int b0_n4 = ac0 & 31, b0_k = ac0 >> 5;
    const int b1_n4 = ac1 & 31, b1_k = ac1 >> 5;

    const float* Ag0 = g_hs + (size_t)(t0 + a0_t) * (B_ * H_) + a0_k * 16 + a0_bh * 4;
    const float* Ag1 = g_hs + (size_t)(t0 + a1_t) * (B_ * H_) + a1_k * 16 + a1_bh * 4;
    const float* Bg0 = g_WyT + (size_t)b0_k * V_ + n0 + b0_n4 * 4;
    const float* Bg1 = g_WyT + (size_t)b1_k * V_ + n0 + b1_n4 * 4;

    uint32_t sA0[2], sA1[2], sB0[2], sB1[2];
    #pragma unroll
    for (int s = 0; s < 2; s++) {
        sA0[s] = smem_u32(&As[s][a0_k][a0_t * 16 + a0_bh * 4]);
        sA1[s] = smem_u32(&As[s][a1_k][a1_t * 16 + a1_bh * 4]);
        sB0[s] = smem_u32(&Bs[s][b0_k][b0_n4 * 4]);
        sB1[s] = smem_u32(&Bs[s][b1_k][b1_n4 * 4]);
    }

    unsigned long long acc[8][4];
    #pragma unroll
    for (int i = 0; i < 8; i++)
        #pragma unroll
        for (int jj = 0; jj < 4; jj++) acc[i][jj] = 0ull;

    // prologue: stage 0
    cp16(sA0[0], Ag0);  cp16(sA1[0], Ag1);
    cp16(sB0[0], Bg0);  cp16(sB1[0], Bg1);
    asm volatile("cp.async.commit_group;" ::: "memory");

    #pragma unroll 1
    for (int kt = 0; kt < H_ / BK; kt++) {
        const int cur = kt & 1;
        if (kt < H_ / BK - 1) {
            const int nxt = cur ^ 1;
            size_t aoff = (size_t)(kt + 1) * (BK * 16);     // A k-advance
            size_t boff = (size_t)(kt + 1) * (BK * V_);     // B k-advance
            cp16(sA0[nxt], Ag0 + aoff);  cp16(sA1[nxt], Ag1 + aoff);
            cp16(sB0[nxt], Bg0 + boff);  cp16(sB1[nxt], Bg1 + boff);
            asm volatile("cp.async.commit_group;" ::: "memory");
            asm volatile("cp.async.wait_group 1;" ::: "memory");
        } else {
            asm volatile("cp.async.wait_group 0;" ::: "memory");
        }
        __syncthreads();

        #pragma unroll
        for (int k = 0; k < BK; k++) {
            float4 aq0 = *(const float4*)&As[cur][k][tm * 4];
            float4 aq1 = *(const float4*)&As[cur][k][64 + tm * 4];
            ulonglong2 b01 = *(const ulonglong2*)&Bs[cur][k][tn * 4];
            ulonglong2 b23 = *(const ulonglong2*)&Bs[cur][k][64 + tn * 4];
            unsigned long long b2[4] = { b01.x, b01.y, b23.x, b23.y };
            float am[8] = { aq0.x, aq0.y, aq0.z, aq0.w,
                            aq1.x, aq1.y, aq1.z, aq1.w };
            #pragma unroll
            for (int i = 0; i < 8; i++) {
                unsigned long long a2 = pack2(am[i], am[i]);
                #pragma unroll
                for (int jj = 0; jj < 4; jj++) fma2(acc[i][jj], a2, b2[jj]);
            }
        }
        __syncthreads();
    }

    // ---- epilogue: bias + scatter to logits [b][t][v] (verified R9) ----
    float4 bias0 = __ldg((const float4*)(Wyb + n0 + tn * 4));
    float4 bias1 = __ldg((const float4*)(Wyb + n0 + 64 + tn * 4));
    #pragma unroll
    for (int i = 0; i < 8; i++) {
        int m_tile = (i < 4) ? (tm * 4 + i) : (64 + tm * 4 + (i - 4));
        int m  = t0 * 16 + m_tile;
        int tt = m >> 4;
        int bb = m & 15;
        float* orow = out + ((size_t)bb * T_ + tt) * V_ + n0;
        float l0, h0v, l1, h1v;
        unpack2(acc[i][0], l0, h0v);
        unpack2(acc[i][1], l1, h1v);
        float4 v0 = make_float4(l0 + bias0.x, h0v + bias0.y,
                                l1 + bias0.z, h1v + bias0.w);
        *(float4*)(orow + tn * 4) = v0;
        unpack2(acc[i][2], l0, h0v);
        unpack2(acc[i][3], l1, h1v);
        float4 v1 = make_float4(l0 + bias1.x, h0v + bias1.y,
                                l1 + bias1.z, h1v + bias1.w);
        *(float4*)(orow + 64 + tn * 4) = v1;
    }
}

// ---------------------------------------------------------------------------
// Launch
// ---------------------------------------------------------------------------
extern "C" void kernel_launch(void* const* d_in, const int* in_sizes, int n_in,
                              void* d_out, int out_size) {
    const int*   x   = (const int*)  d_in[0];   // [B,T] int32
    const float* h0  = (const float*)d_in[1];   // [B,H]
    const float* Wx  = (const float*)d_in[2];   // [H,V]
    const float* Wxb = (const float*)d_in[3];   // [H]
    const float* Wh  = (const float*)d_in[4];   // [H,H]
    const float* Wy  = (const float*)d_in[5];   // [V,H]
    const float* Wyb = (const float*)d_in[6];   // [V]
    float* out = (float*)d_out;

    // B transpose for the GEMM (one-shot, ~60 us)
    transpose_wy_kernel<<<dim3(V_ / 32, H_ / 32), 256>>>(Wy);

    const int smem_rnn = (B_ * H_ + 8 * H_) * (int)sizeof(float);   // 96 KB
    cudaFuncSetAttribute(rnn_recurrence_kernel,
                         cudaFuncAttributeMaxDynamicSharedMemorySize, smem_rnn);
    rnn_recurrence_kernel<<<NBLK, 128, smem_rnn>>>(x, h0, Wx, Wxb, Wh,
                                                   out, out_size);

    dim3 grid(V_ / 128, (T_ * B_) / 128);   // (64, 128)
    gemm_logits_kernel<<<grid, 256>>>(Wyb, out);
}